// round 10
// baseline (speedup 1.0000x reference)
#include <cuda_runtime.h>
#include <cuda_fp16.h>
#include <cstdint>

#define NSAMPLES   524288
#define NFEAT      64
#define NGATES     64
#define NOUT       8
#define BASEN      66
#define MAXCONN    130
#define BLK        128            // threads per block
#define SPB        256            // samples per tile (2/thread, half2)
#define ROWB       512            // bytes per entry row
#define CAPG       30             // live gate rows cap (proven ok in R8/R9)
#define CAPX       57             // live X rows cap   (proven ok in R8/R9)
#define GROW0      3              // rows: 0 trash, 1 const0, 2 const1, 3.. gates
#define XROW0      (GROW0 + CAPG)          // 33
#define NROWS      (XROW0 + CAPX)          // 90 rows = 46080 B
#define GARR_OFF   (NROWS * ROWB)          // gate descriptors: 64 x uint4 = 1024 B
#define XOFF_OFF   (GARR_OFF + 1024)       // X row offsets: 64 x u32 = 256 B
#define W2_OFF     (XOFF_OFF + 256)        // weights (w,w): 64*8*8 = 4096 B
#define FLAG_OFF   (W2_OFF + 4096)
#define SMEM_TOT   (FLAG_OFF + 16)         // 51472 B -> 4 blocks/SM, 16 warps
#define NT         (NSAMPLES / SPB)        // 2048 tiles
#define GRID       592                     // 148 SMs * 4 persistent blocks

// XOR swizzle keyed on ORIGINAL entry index e: phys = logical ^ (8*((e>>2)&15)).
// Proven conflict-free for gate LDS/STS.32 and transpose STS.64 in R8/R9.

static __device__ __forceinline__ unsigned pack_h2(float a, float b) {
    __half2 h = __floats2half2_rn(a, b);
    __half2_raw r = *reinterpret_cast<__half2_raw*>(&h);
    return (unsigned)r.x | ((unsigned)r.y << 16);
}

// ---------------------------------------------------------------------------
// ONE kernel. Prologue (per block): top-2 of masked logits (softmax monotonic
// => top-2 of raw logits; lexicographic tie-break matches top_k), two-pool
// compaction via ballot/popc, weight fold — all into THIS block's smem.
// Then a persistent tile loop identical in spirit to R8's fast path, but with
// weights + gate descriptors read from smem (uniform broadcast LDS) instead
// of the half-rate constant port.
// ---------------------------------------------------------------------------
__global__ void __launch_bounds__(BLK, 4)
fused_kernel(const float* __restrict__ X,  const float* __restrict__ gw,
             const float* __restrict__ ow, const float* __restrict__ sc,
             float* __restrict__ out) {
    extern __shared__ char sb[];
    const int tid = threadIdx.x;

    // scratch (rows 0-2 region, dead until tiles start)
    int* si1 = (int*)(sb);                       // 64 ints
    int* si2 = (int*)(sb + 256);                 // 64 ints
    unsigned char* needf = (unsigned char*)(sb + 512);   // 130 B
    int* xrow = (int*)(sb + 768);                // 64 ints
    int* grow = (int*)(sb + 1024);               // 64 ints
    unsigned* flagp = (unsigned*)(sb + FLAG_OFF);

    if (tid < MAXCONN) needf[tid] = 0;

    // --- top-2 per gate: 2 threads/gate, shfl_xor(1) merge ---
    {
        const int gate = tid >> 1, half = tid & 1;
        const float* row = gw + gate * MAXCONN;
        const int n = BASEN + gate;
        float v1 = -3.4e38f, v2 = -3.4e38f;
        int   i1 = 0x7fffffff, i2 = 0x7fffffff;
#pragma unroll 4
        for (int j = half; j < n; j += 2) {
            float v = row[j];
            if (v > v1 || (v == v1 && j < i1)) { v2 = v1; i2 = i1; v1 = v; i1 = j; }
            else if (v > v2 || (v == v2 && j < i2)) { v2 = v; i2 = j; }
        }
        float ov1 = __shfl_xor_sync(0xffffffffu, v1, 1);
        int   oi1 = __shfl_xor_sync(0xffffffffu, i1, 1);
        float ov2 = __shfl_xor_sync(0xffffffffu, v2, 1);
        int   oi2 = __shfl_xor_sync(0xffffffffu, i2, 1);
        if (ov1 > v1 || (ov1 == v1 && oi1 < i1)) { v2 = v1; i2 = i1; v1 = ov1; i1 = oi1; }
        else if (ov1 > v2 || (ov1 == v2 && oi1 < i2)) { v2 = ov1; i2 = oi1; }
        if (ov2 > v1 || (ov2 == v1 && oi2 < i1)) { v2 = v1; i2 = i1; v1 = ov2; i1 = oi2; }
        else if (ov2 > v2 || (ov2 == v2 && oi2 < i2)) { v2 = ov2; i2 = oi2; }
        if (half == 0) { si1[gate] = i1; si2[gate] = i2; }
    }
    __syncthreads();
    if (tid < NGATES) { needf[si1[tid]] = 1; needf[si2[tid]] = 1; }
    __syncthreads();

    if (tid < 32) {                  // two-pool prefix compaction (warp 0)
        int runX = 0;
#pragma unroll
        for (int ch = 0; ch < 2; ++ch) {
            int e = ch * 32 + tid;
            bool nd = needf[e] != 0;
            unsigned mask = __ballot_sync(0xffffffffu, nd);
            xrow[e] = nd ? (XROW0 + runX + __popc(mask & ((1u << tid) - 1u))) : 0;
            runX += __popc(mask);
        }
        int runG = 0;
#pragma unroll
        for (int ch = 0; ch < 2; ++ch) {
            int g = ch * 32 + tid;
            bool nd = needf[BASEN + g] != 0;
            unsigned mask = __ballot_sync(0xffffffffu, nd);
            grow[g] = nd ? (GROW0 + runG + __popc(mask & ((1u << tid) - 1u))) : 0;
            runG += __popc(mask);
        }
        if (tid == 0) *flagp = (runX > CAPX || runG > CAPG) ? 1u : 0u;
    }
    __syncthreads();
    const unsigned flags = *flagp;

    // --- build descriptor tables in smem ---
    if (tid < NGATES) {
        int e1 = si1[tid], e2 = si2[tid];
        if (!flags) {
            auto rowOf = [&](int e) -> unsigned {
                if (e < 64)  return (unsigned)xrow[e];
                if (e == 64) return 1u;
                if (e == 65) return 2u;
                return (unsigned)grow[e - BASEN];
            };
            unsigned offA = rowOf(e1) * ROWB, offB = rowOf(e2) * ROWB;
            unsigned swzA = 8u * (unsigned)((e1 >> 2) & 15);
            unsigned swzB = 8u * (unsigned)((e2 >> 2) & 15);
            unsigned sOff = grow[tid] ? (unsigned)(grow[tid] * ROWB) : 0u;
            ((uint4*)(sb + GARR_OFF))[tid] =
                make_uint4(offA, swzA | (sOff << 8), offB, swzB);
            ((unsigned*)(sb + XOFF_OFF))[tid] =
                xrow[tid] ? (unsigned)(xrow[tid] * ROWB) : 0u;
        } else {
            ((uint4*)(sb + GARR_OFF))[tid] =
                make_uint4((unsigned)e1, (unsigned)e2, 0u, 0u);
        }
    }
#pragma unroll
    for (int k = tid; k < NGATES * NOUT; k += BLK) {
        float wv = ow[k] * sc[k & 7];
        ((float2*)(sb + W2_OFF))[k] = make_float2(wv, wv);
    }
    __syncthreads();                 // scratch rows done; tables committed

    // =========================== FALLBACK PATH =============================
    // (capacity overflow only — never taken for this dataset; correct & slow)
    if (flags) {
        for (long long s = (long long)blockIdx.x * BLK + tid; s < NSAMPLES;
             s += (long long)GRID * BLK) {
            float buf[MAXCONN];
            const float* xr = X + s * NFEAT;
#pragma unroll
            for (int f = 0; f < NFEAT; ++f) buf[f] = xr[f];
            buf[64] = 0.0f; buf[65] = 1.0f;
            float acc[NOUT];
#pragma unroll
            for (int j = 0; j < NOUT; ++j) acc[j] = 0.0f;
            for (int i = 0; i < NGATES; ++i) {
                uint4 o = ((const uint4*)(sb + GARR_OFF))[i];
                float g = fmaf(-buf[o.x], buf[o.y], 1.0f);
                buf[BASEN + i] = g;
#pragma unroll
                for (int j = 0; j < NOUT; ++j)
                    acc[j] = fmaf(g, ((const float2*)(sb + W2_OFF))[i * 8 + j].x, acc[j]);
            }
            float4* op = (float4*)(out + s * NOUT);
            op[0] = make_float4(acc[0], acc[1], acc[2], acc[3]);
            op[1] = make_float4(acc[4], acc[5], acc[6], acc[7]);
        }
        return;
    }

    // ============================= FAST PATH ================================
    const unsigned m = 4u * tid;            // sample-pair byte offset in a row
    const int c  = tid & 15;                // feature chunk: features 4c..4c+3
    const int hh = (tid >> 4) & 1;
    const int wq = tid >> 5;
    const unsigned swz = 8u * (unsigned)c;

    unsigned xo[4];
#pragma unroll
    for (int f = 0; f < 4; ++f) xo[f] = ((const unsigned*)(sb + XOFF_OFF))[4 * c + f];

    *(__half2*)(sb + 1 * ROWB + m) = __floats2half2_rn(0.0f, 0.0f);  // swz(64)=0
    *(__half2*)(sb + 2 * ROWB + m) = __floats2half2_rn(1.0f, 1.0f);  // swz(65)=0

    for (long long t = blockIdx.x; t < NT; t += GRID) {
        // --- X load + fp16 transpose into compact rows ---
        const float4* Xb = (const float4*)(X + t * SPB * NFEAT);
#pragma unroll
        for (int r = 0; r < 8; ++r) {
            int sq = 16 * wq + 8 * hh + r;              // sample quad 0..63
            const float4* rp = Xb + (4 * sq) * 16 + c;
            float4 v0 = __ldcs(rp + 0 * 16);
            float4 v1 = __ldcs(rp + 1 * 16);
            float4 v2 = __ldcs(rp + 2 * 16);
            float4 v3 = __ldcs(rp + 3 * 16);
            unsigned so = (8u * (unsigned)sq) ^ swz;
            if (xo[0]) *(uint2*)(sb + xo[0] + so) =
                make_uint2(pack_h2(v0.x, v1.x), pack_h2(v2.x, v3.x));
            if (xo[1]) *(uint2*)(sb + xo[1] + so) =
                make_uint2(pack_h2(v0.y, v1.y), pack_h2(v2.y, v3.y));
            if (xo[2]) *(uint2*)(sb + xo[2] + so) =
                make_uint2(pack_h2(v0.z, v1.z), pack_h2(v2.z, v3.z));
            if (xo[3]) *(uint2*)(sb + xo[3] + so) =
                make_uint2(pack_h2(v0.w, v1.w), pack_h2(v2.w, v3.w));
        }
        __syncthreads();

        // --- gate loop: all tables from smem (broadcast LDS, no LDC) ---
        unsigned long long acc[NOUT];
#pragma unroll
        for (int j = 0; j < NOUT; ++j) acc[j] = 0ULL;

        uint4 o = ((const uint4*)(sb + GARR_OFF))[0];
        __half2 ah = *(const __half2*)(sb + o.x + (m ^ (o.y & 0xFFu)));
        __half2 bh = *(const __half2*)(sb + o.z + (m ^ o.w));

#pragma unroll
        for (int i = 0; i < NGATES; ++i) {
            float2 af = __half22float2(ah);
            float2 bf = __half22float2(bh);
            float gx = fmaf(-af.x, bf.x, 1.0f);
            float gy = fmaf(-af.y, bf.y, 1.0f);

            unsigned sOff = o.y >> 8;       // 0 => dead gate: skip STS
            const unsigned swzS = 8u * (unsigned)(((BASEN + i) >> 2) & 15);
            if (sOff) *(__half2*)(sb + sOff + (m ^ swzS)) = __floats2half2_rn(gx, gy);

            if (i + 1 < NGATES) {           // post-STS prefetch: never stale
                o = ((const uint4*)(sb + GARR_OFF))[i + 1];
                ah = *(const __half2*)(sb + o.x + (m ^ (o.y & 0xFFu)));
                bh = *(const __half2*)(sb + o.z + (m ^ o.w));
            }

            unsigned long long gg;
            asm("mov.b64 %0, {%1, %2};" : "=l"(gg) : "f"(gx), "f"(gy));
            const ulonglong2* wp = (const ulonglong2*)(sb + W2_OFF + (unsigned)(i * 64));
#pragma unroll
            for (int q = 0; q < 4; ++q) {   // 4x LDS.128, 8x FMA.f32x2
                ulonglong2 w = wp[q];
                asm("fma.rn.f32x2 %0, %1, %2, %0;" : "+l"(acc[2*q+0]) : "l"(gg), "l"(w.x));
                asm("fma.rn.f32x2 %0, %1, %2, %0;" : "+l"(acc[2*q+1]) : "l"(gg), "l"(w.y));
            }
        }

        float s0[NOUT], s1[NOUT];
#pragma unroll
        for (int j = 0; j < NOUT; ++j)
            asm("mov.b64 {%0, %1}, %2;" : "=f"(s0[j]), "=f"(s1[j]) : "l"(acc[j]));
        float4* op = (float4*)(out + (t * SPB + 2 * tid) * NOUT);
        __stcs(&op[0], make_float4(s0[0], s0[1], s0[2], s0[3]));
        __stcs(&op[1], make_float4(s0[4], s0[5], s0[6], s0[7]));
        __stcs(&op[2], make_float4(s1[0], s1[1], s1[2], s1[3]));
        __stcs(&op[3], make_float4(s1[4], s1[5], s1[6], s1[7]));

        __syncthreads();                    // protect X rows before next load
    }
}

// ---------------------------------------------------------------------------
// Launch: ONE kernel node. No prep, no memcpy, no fallback launch.
// ---------------------------------------------------------------------------
extern "C" void kernel_launch(void* const* d_in, const int* in_sizes, int n_in,
                              void* d_out, int out_size) {
    const float* X  = (const float*)d_in[0];  // (524288, 64)
    const float* gw = (const float*)d_in[1];  // (64, 130)
    const float* ow = (const float*)d_in[2];  // (64, 8)
    const float* sc = (const float*)d_in[3];  // (8,)
    float* out = (float*)d_out;               // (524288, 8)

    cudaFuncSetAttribute((const void*)fused_kernel,
                         cudaFuncAttributeMaxDynamicSharedMemorySize, SMEM_TOT);

    fused_kernel<<<GRID, BLK, SMEM_TOT>>>(X, gw, ow, sc, out);
}

// round 11
// speedup vs baseline: 1.0152x; 1.0152x over previous
#include <cuda_runtime.h>
#include <cuda_fp16.h>
#include <cstdint>

#define NSAMPLES   524288
#define NFEAT      64
#define NGATES     64
#define NOUT       8
#define BASEN      66
#define MAXCONN    130
#define BLK        128            // threads per block
#define SPB        256            // samples per tile (2/thread, half2)
#define ROWB       512            // bytes per entry row
#define CAPG       30             // live gate rows cap (proven R8/R9)
#define CAPX       57             // live X rows cap   (proven R8/R9)
#define GROW0      3              // rows: 0 unused, 1 const0, 2 const1, 3.. gates
#define XROW0      (GROW0 + CAPG)     // 33
#define NROWS      (XROW0 + CAPX)     // 90 rows
#define SMEM_FAST  (NROWS * ROWB)     // 46080 B -> 4 blocks/SM
#define NT         (NSAMPLES / SPB)   // 2048 blocks

// XOR swizzle keyed on ORIGINAL entry index e: phys = logical ^ (8*((e>>2)&15)).
// Proven conflict-free for gate LDS/STS.32 and transpose STS.64 (R8-R10).

struct Params {
    // per gate: x = offA, y = swzA | (storeOff<<8) | (depA<<31),
    //           z = offB, w = swzB | (depB<<31)
    // dep flags only meaningful for odd gates: operand == previous gate.
    uint4    gd[NGATES];
    uint2    forig[NGATES];     // raw entry indices (fallback path)
    unsigned xoff[NFEAT];       // X row byte offset; 0 = dead feature
    unsigned flags, pad;
    float2   w2[NGATES][NOUT];  // (w,w) duplicated for f32x2 FMA
};
__device__   Params g_stage;
__constant__ Params c_p;

// ---------------------------------------------------------------------------
// Prep (64 threads): serial top-2 per gate (R3-proven: softmax is monotonic so
// top-2 of raw masked logits; strict '>' = top_k lower-index tie-break), then
// one-warp ballot compaction + descriptor/weight build.
// ---------------------------------------------------------------------------
__global__ void __launch_bounds__(64)
prep_kernel(const float* __restrict__ gw,
            const float* __restrict__ ow,
            const float* __restrict__ sc) {
    __shared__ int si1[NGATES], si2[NGATES];
    __shared__ int xrow[NFEAT], grow[NGATES];
    __shared__ unsigned char needf[MAXCONN];
    const int tid = threadIdx.x;

    for (int e = tid; e < MAXCONN; e += 64) needf[e] = 0;

    const float* row = gw + tid * MAXCONN;
    const int n = BASEN + tid;
    float v1 = -3.4e38f, v2 = -3.4e38f;
    int   i1 = 0, i2 = 0;
    for (int j = 0; j < n; ++j) {
        float v = row[j];
        if (v > v1)      { v2 = v1; i2 = i1; v1 = v; i1 = j; }
        else if (v > v2) { v2 = v;  i2 = j; }
    }
    si1[tid] = i1; si2[tid] = i2;
    __syncthreads();
    needf[si1[tid]] = 1; needf[si2[tid]] = 1;
    __syncthreads();

    if (tid < 32) {                         // two-pool prefix compaction
        int runX = 0;
#pragma unroll
        for (int ch = 0; ch < 2; ++ch) {
            int e = ch * 32 + tid;
            bool nd = needf[e] != 0;
            unsigned mask = __ballot_sync(0xffffffffu, nd);
            xrow[e] = nd ? (XROW0 + runX + __popc(mask & ((1u << tid) - 1u))) : 0;
            runX += __popc(mask);
        }
        int runG = 0;
#pragma unroll
        for (int ch = 0; ch < 2; ++ch) {
            int g = ch * 32 + tid;
            bool nd = needf[BASEN + g] != 0;
            unsigned mask = __ballot_sync(0xffffffffu, nd);
            grow[g] = nd ? (GROW0 + runG + __popc(mask & ((1u << tid) - 1u))) : 0;
            runG += __popc(mask);
        }
        if (tid == 0) g_stage.flags = (runX > CAPX || runG > CAPG) ? 1u : 0u;
    }
    __syncthreads();

    {
        int e1 = si1[tid], e2 = si2[tid];
        auto rowOf = [&](int e) -> unsigned {
            if (e < 64)  return (unsigned)xrow[e];
            if (e == 64) return 1u;
            if (e == 65) return 2u;
            return (unsigned)grow[e - BASEN];
        };
        unsigned offA = rowOf(e1) * ROWB, offB = rowOf(e2) * ROWB;
        unsigned swzA = 8u * (unsigned)((e1 >> 2) & 15);
        unsigned swzB = 8u * (unsigned)((e2 >> 2) & 15);
        unsigned st   = grow[tid] ? (unsigned)(grow[tid] * ROWB) : 0u;
        unsigned depA = ((tid & 1) && e1 == BASEN + tid - 1) ? 1u : 0u;
        unsigned depB = ((tid & 1) && e2 == BASEN + tid - 1) ? 1u : 0u;
        g_stage.gd[tid] = make_uint4(offA, swzA | (st << 8) | (depA << 31),
                                     offB, swzB | (depB << 31));
        g_stage.forig[tid] = make_uint2((unsigned)e1, (unsigned)e2);
    }
    if (tid < NFEAT)
        g_stage.xoff[tid] = xrow[tid] ? (unsigned)(xrow[tid] * ROWB) : 0u;
#pragma unroll
    for (int j = 0; j < NOUT; ++j) {
        float wv = ow[tid * NOUT + j] * sc[j];
        g_stage.w2[tid][j] = make_float2(wv, wv);
    }
}

static __device__ __forceinline__ unsigned pack_h2(float a, float b) {
    __half2 h = __floats2half2_rn(a, b);
    __half2_raw r = *reinterpret_cast<__half2_raw*>(&h);
    return (unsigned)r.x | ((unsigned)r.y << 16);
}

// ---------------------------------------------------------------------------
// Fast kernel: fp16 buffer, 2 samples/thread, DUAL-GATE pairs with hfma2.
// Chain per pair: LDSx2(overlapped) -> HFMA2 -> (pred mov) -> HFMA2 -> STS;
// no F2F conversions on the chain (fp32 only in the off-chain accumulation).
// Tables (descriptors + weights) via the constant port (LDC), off L1.
// ---------------------------------------------------------------------------
__global__ void __launch_bounds__(BLK, 4)
fast_kernel(const float* __restrict__ X, float* __restrict__ out) {
    // ---------- fallback branch (capacity overflow; never for this data) ----
    if (c_p.flags) {
        const long long s0 = (long long)blockIdx.x * BLK + threadIdx.x;
        for (int rep = 0; rep < 2; ++rep) {
            long long s = s0 + (long long)rep * NT * BLK;
            if (s >= NSAMPLES) break;
            float buf[MAXCONN];
            const float* xr = X + s * NFEAT;
#pragma unroll
            for (int f = 0; f < NFEAT; ++f) buf[f] = xr[f];
            buf[64] = 0.0f; buf[65] = 1.0f;
            float acc[NOUT];
#pragma unroll
            for (int j = 0; j < NOUT; ++j) acc[j] = 0.0f;
            for (int i = 0; i < NGATES; ++i) {
                uint2 o = c_p.forig[i];
                float g = fmaf(-buf[o.x], buf[o.y], 1.0f);
                buf[BASEN + i] = g;
#pragma unroll
                for (int j = 0; j < NOUT; ++j)
                    acc[j] = fmaf(g, c_p.w2[i][j].x, acc[j]);
            }
            float4* op = (float4*)(out + s * NOUT);
            op[0] = make_float4(acc[0], acc[1], acc[2], acc[3]);
            op[1] = make_float4(acc[4], acc[5], acc[6], acc[7]);
        }
        return;
    }

    // ------------------------------ fast path -------------------------------
    extern __shared__ char sb[];
    const int tid = threadIdx.x;
    const long long base = (long long)blockIdx.x * SPB;

    // X transpose: LDG.128 quads -> fp16 pack -> STS.64 (R8-proven, CF swizzle)
    {
        const int c  = tid & 15;
        const int h  = (tid >> 4) & 1;
        const int wq = tid >> 5;
        const float4* Xb = (const float4*)(X + base * NFEAT);
        unsigned xo0 = c_p.xoff[4 * c + 0];
        unsigned xo1 = c_p.xoff[4 * c + 1];
        unsigned xo2 = c_p.xoff[4 * c + 2];
        unsigned xo3 = c_p.xoff[4 * c + 3];
        const unsigned swz = 8u * (unsigned)c;
#pragma unroll
        for (int r = 0; r < 8; ++r) {
            int sq = 16 * wq + 8 * h + r;
            const float4* rp = Xb + (4 * sq) * 16 + c;
            float4 v0 = __ldcs(rp + 0 * 16);
            float4 v1 = __ldcs(rp + 1 * 16);
            float4 v2 = __ldcs(rp + 2 * 16);
            float4 v3 = __ldcs(rp + 3 * 16);
            unsigned so = (8u * (unsigned)sq) ^ swz;
            if (xo0) *(uint2*)(sb + xo0 + so) =
                make_uint2(pack_h2(v0.x, v1.x), pack_h2(v2.x, v3.x));
            if (xo1) *(uint2*)(sb + xo1 + so) =
                make_uint2(pack_h2(v0.y, v1.y), pack_h2(v2.y, v3.y));
            if (xo2) *(uint2*)(sb + xo2 + so) =
                make_uint2(pack_h2(v0.z, v1.z), pack_h2(v2.z, v3.z));
            if (xo3) *(uint2*)(sb + xo3 + so) =
                make_uint2(pack_h2(v0.w, v1.w), pack_h2(v2.w, v3.w));
        }
    }
    const unsigned m = 4u * tid;               // sample-pair byte offset
    *(__half2*)(sb + 1 * ROWB + m) = __floats2half2_rn(0.0f, 0.0f); // swz(64)=0
    *(__half2*)(sb + 2 * ROWB + m) = __floats2half2_rn(1.0f, 1.0f); // swz(65)=0
    __syncthreads();

    const __half2 one2 = __float2half2_rn(1.0f);
    unsigned long long acc[NOUT];
#pragma unroll
    for (int j = 0; j < NOUT; ++j) acc[j] = 0ULL;

    uint4 pA = c_p.gd[0], pB = c_p.gd[1];
    __half2 a1 = *(const __half2*)(sb + pA.x + (m ^ (pA.y & 0xFFu)));
    __half2 b1 = *(const __half2*)(sb + pA.z + (m ^ (pA.w & 0xFFu)));
    __half2 a2 = *(const __half2*)(sb + pB.x + (m ^ (pB.y & 0xFFu)));
    __half2 b2 = *(const __half2*)(sb + pB.z + (m ^ (pB.w & 0xFFu)));

#pragma unroll
    for (int k = 0; k < NGATES / 2; ++k) {
        __half2 g1 = __hfma2(__hneg2(a1), b1, one2);      // gate 2k
        if (pB.y & 0x80000000u) a2 = g1;                  // in-pair forward
        if (pB.w & 0x80000000u) b2 = g1;
        __half2 g2 = __hfma2(__hneg2(a2), b2, one2);      // gate 2k+1

        unsigned s1 = (pA.y >> 8) & 0x7FFFu;              // 0 => dead gate
        unsigned s2 = (pB.y >> 8) & 0x7FFFu;
        const unsigned z1 = 8u * (unsigned)(((BASEN + 2 * k)     >> 2) & 15);
        const unsigned z2 = 8u * (unsigned)(((BASEN + 2 * k + 1) >> 2) & 15);
        if (s1) *(__half2*)(sb + s1 + (m ^ z1)) = g1;
        if (s2) *(__half2*)(sb + s2 + (m ^ z2)) = g2;

        if (k + 1 < NGATES / 2) {            // post-STS prefetch: never stale
            pA = c_p.gd[2 * k + 2];
            pB = c_p.gd[2 * k + 3];
            a1 = *(const __half2*)(sb + pA.x + (m ^ (pA.y & 0xFFu)));
            b1 = *(const __half2*)(sb + pA.z + (m ^ (pA.w & 0xFFu)));
            a2 = *(const __half2*)(sb + pB.x + (m ^ (pB.y & 0xFFu)));
            b2 = *(const __half2*)(sb + pB.z + (m ^ (pB.w & 0xFFu)));
        }

        // Off-chain fp32 accumulation (f32x2, duplicated weights via LDC.128)
        float2 f1 = __half22float2(g1);
        float2 f2 = __half22float2(g2);
        unsigned long long gg1, gg2;
        asm("mov.b64 %0, {%1, %2};" : "=l"(gg1) : "f"(f1.x), "f"(f1.y));
        asm("mov.b64 %0, {%1, %2};" : "=l"(gg2) : "f"(f2.x), "f"(f2.y));
        const ulonglong2* w1p = (const ulonglong2*)&c_p.w2[2 * k][0];
        const ulonglong2* w2p = (const ulonglong2*)&c_p.w2[2 * k + 1][0];
#pragma unroll
        for (int q = 0; q < 4; ++q) {
            ulonglong2 wa = w1p[q], wb = w2p[q];
            asm("fma.rn.f32x2 %0, %1, %2, %0;" : "+l"(acc[2*q+0]) : "l"(gg1), "l"(wa.x));
            asm("fma.rn.f32x2 %0, %1, %2, %0;" : "+l"(acc[2*q+1]) : "l"(gg1), "l"(wa.y));
            asm("fma.rn.f32x2 %0, %1, %2, %0;" : "+l"(acc[2*q+0]) : "l"(gg2), "l"(wb.x));
            asm("fma.rn.f32x2 %0, %1, %2, %0;" : "+l"(acc[2*q+1]) : "l"(gg2), "l"(wb.y));
        }
    }

    float s0[NOUT], s1v[NOUT];
#pragma unroll
    for (int j = 0; j < NOUT; ++j)
        asm("mov.b64 {%0, %1}, %2;" : "=f"(s0[j]), "=f"(s1v[j]) : "l"(acc[j]));
    float4* op = (float4*)(out + (base + 2 * tid) * NOUT);
    __stcs(&op[0], make_float4(s0[0], s0[1], s0[2], s0[3]));
    __stcs(&op[1], make_float4(s0[4], s0[5], s0[6], s0[7]));
    __stcs(&op[2], make_float4(s1v[0], s1v[1], s1v[2], s1v[3]));
    __stcs(&op[3], make_float4(s1v[4], s1v[5], s1v[6], s1v[7]));
}

// ---------------------------------------------------------------------------
// Launch: prep -> one constant memcpy -> fast (3 nodes).
// ---------------------------------------------------------------------------
extern "C" void kernel_launch(void* const* d_in, const int* in_sizes, int n_in,
                              void* d_out, int out_size) {
    const float* X  = (const float*)d_in[0];  // (524288, 64)
    const float* gw = (const float*)d_in[1];  // (64, 130)
    const float* ow = (const float*)d_in[2];  // (64, 8)
    const float* sc = (const float*)d_in[3];  // (8,)
    float* out = (float*)d_out;               // (524288, 8)

    cudaFuncSetAttribute((const void*)fast_kernel,
                         cudaFuncAttributeMaxDynamicSharedMemorySize, SMEM_FAST);

    prep_kernel<<<1, 64>>>(gw, ow, sc);

    void* gp = nullptr;
    cudaGetSymbolAddress(&gp, g_stage);
    cudaMemcpyToSymbolAsync(c_p, gp, sizeof(Params), 0,
                            cudaMemcpyDeviceToDevice, 0);

    fast_kernel<<<NT, BLK, SMEM_FAST>>>(X, out);
}